// round 6
// baseline (speedup 1.0000x reference)
#include <cuda_runtime.h>
#include <cuda_bf16.h>
#include <math.h>
#include <cstdint>

// Problem constants
#define BB 4
#define SS 2048
#define DD 1024
#define HH 16
#define MM (BB*SS)          // 8192
#define HD 1024             // H*DK

typedef __nv_bfloat16 bf16;

// ---------------- scratch (__device__ globals; no allocs allowed) ----------
__device__ bf16 g_qh[MM*DD], g_ql[MM*DD];          // input splits
__device__ bf16 g_kh[MM*DD], g_kl[MM*DD];
__device__ bf16 g_vh[MM*DD], g_vl[MM*DD];
__device__ bf16 g_wh[4][DD*HD], g_wl[4][DD*HD];    // weights^T [N][K] hi/lo
__device__ bf16 g_pqh[MM*HD], g_pql[MM*HD];        // projected Q (pre-scaled)
__device__ bf16 g_pkh[MM*HD], g_pkl[MM*HD];        // projected K
__device__ bf16 g_pvh[MM*HD], g_pvl[MM*HD];        // projected V
__device__ bf16 g_poh[MM*HD], g_pol[MM*HD];        // attention output

// Q pre-scale: (1/sqrt(64)) * log2(e)  — lets softmax use raw ex2
#define QSCALE 0.180336880f

// ---------------- PTX helpers ----------------------------------------------
__device__ __forceinline__ uint32_t smem_u32(const void* p) {
    uint32_t a;
    asm("{ .reg .u64 t; cvta.to.shared.u64 t, %1; cvt.u32.u64 %0, t; }"
        : "=r"(a) : "l"(p));
    return a;
}
__device__ __forceinline__ void cpa16(uint32_t s, const void* g) {
    asm volatile("cp.async.cg.shared.global [%0], [%1], 16;" :: "r"(s), "l"(g));
}
__device__ __forceinline__ void cpa_commit() {
    asm volatile("cp.async.commit_group;" ::: "memory");
}
__device__ __forceinline__ void ldsm4(uint32_t* r, uint32_t a) {
    asm volatile("ldmatrix.sync.aligned.m8n8.x4.shared.b16 {%0,%1,%2,%3}, [%4];"
                 : "=r"(r[0]), "=r"(r[1]), "=r"(r[2]), "=r"(r[3]) : "r"(a));
}
__device__ __forceinline__ void ldsm4t(uint32_t* r, uint32_t a) {
    asm volatile("ldmatrix.sync.aligned.m8n8.x4.trans.shared.b16 {%0,%1,%2,%3}, [%4];"
                 : "=r"(r[0]), "=r"(r[1]), "=r"(r[2]), "=r"(r[3]) : "r"(a));
}
__device__ __forceinline__ void mma16816(float* c, const uint32_t* a,
                                         uint32_t b0, uint32_t b1) {
    asm volatile(
        "mma.sync.aligned.m16n8k16.row.col.f32.bf16.bf16.f32 "
        "{%0,%1,%2,%3}, {%4,%5,%6,%7}, {%8,%9}, {%0,%1,%2,%3};"
        : "+f"(c[0]), "+f"(c[1]), "+f"(c[2]), "+f"(c[3])
        : "r"(a[0]), "r"(a[1]), "r"(a[2]), "r"(a[3]), "r"(b0), "r"(b1));
}
__device__ __forceinline__ uint32_t pk2(float v0, float v1) {
    uint32_t d;
    asm("cvt.rn.bf16x2.f32 %0, %1, %2;" : "=r"(d) : "f"(v1), "f"(v0));
    return d;
}
__device__ __forceinline__ void split2(float v0, float v1, uint32_t& hi, uint32_t& lo) {
    hi = pk2(v0, v1);
    float h0 = __uint_as_float(hi << 16);
    float h1 = __uint_as_float(hi & 0xffff0000u);
    lo = pk2(v0 - h0, v1 - h1);
}
__device__ __forceinline__ float ex2(float x) {
    float y; asm("ex2.approx.f32 %0, %1;" : "=f"(y) : "f"(x)); return y;
}

// ---------------------------------------------------------------------------
// fp32 -> bf16 hi/lo split of q/k/v inputs. blockIdx.y selects tensor.
// ---------------------------------------------------------------------------
__global__ __launch_bounds__(256) void cvt_hl(const float* __restrict__ q,
                                              const float* __restrict__ k,
                                              const float* __restrict__ v)
{
    const int dsel = blockIdx.y;
    const float* src; bf16 *h, *l;
    if      (dsel == 0) { src = q; h = g_qh; l = g_ql; }
    else if (dsel == 1) { src = k; h = g_kh; l = g_kl; }
    else                { src = v; h = g_vh; l = g_vl; }
    int i = blockIdx.x * 256 + threadIdx.x;       // indexes float4
    float4 vv = ((const float4*)src)[i];
    uint32_t h01, l01, h23, l23;
    split2(vv.x, vv.y, h01, l01);
    split2(vv.z, vv.w, h23, l23);
    ((uint32_t*)h)[i*2]   = h01; ((uint32_t*)h)[i*2+1] = h23;
    ((uint32_t*)l)[i*2]   = l01; ((uint32_t*)l)[i*2+1] = l23;
}

// ---------------------------------------------------------------------------
// Weight transpose + hi/lo split. blockIdx.z selects which weight.
// ---------------------------------------------------------------------------
__global__ __launch_bounds__(256) void cvtT(const float* __restrict__ wq,
                                            const float* __restrict__ wk,
                                            const float* __restrict__ wv,
                                            const float* __restrict__ wo)
{
    const int dsel = blockIdx.z;
    const float* W = (dsel == 0) ? wq : (dsel == 1) ? wk : (dsel == 2) ? wv : wo;
    bf16* Th = g_wh[dsel];
    bf16* Tl = g_wl[dsel];
    __shared__ float t[32][33];
    int bx = blockIdx.x * 32;   // n
    int by = blockIdx.y * 32;   // k
    int tx = threadIdx.x & 31, ty = threadIdx.x >> 5;
    for (int i = ty; i < 32; i += 8)
        t[i][tx] = W[(size_t)(by + i) * 1024 + bx + tx];
    __syncthreads();
    for (int i = ty; i < 32; i += 8) {
        float x = t[tx][i];
        bf16 hh = __float2bfloat16_rn(x);
        bf16 ll = __float2bfloat16_rn(x - __bfloat162float(hh));
        Th[(size_t)(bx + i) * 1024 + by + tx] = hh;
        Tl[(size_t)(bx + i) * 1024 + by + tx] = ll;
    }
}

// ---------------------------------------------------------------------------
// HMMA GEMM, hi/lo 3-product, CTA 128x128, BK=32, 8 warps, cp.async 2-stage,
// 2 CTAs/SM. whichArg < 0: which = blockIdx.z (QKV fused).
// ---------------------------------------------------------------------------
#define TEN_B 10240                 // 128 rows * 80B
#define STG_B (4*TEN_B)
#define G_SMEM (2*STG_B)            // 81920

__global__ __launch_bounds__(256, 2) void mmagemm(float* __restrict__ Cout, int whichArg)
{
    extern __shared__ char smem[];
    const int which = (whichArg < 0) ? (int)blockIdx.z : whichArg;
    const bf16 *Ah, *Al, *Bhp, *Blp;
    bf16 *Chi = nullptr, *Clo = nullptr;
    float scale = 1.f;
    if      (which == 0) { Ah=g_qh;  Al=g_ql;  Bhp=g_wh[0]; Blp=g_wl[0]; Chi=g_pqh; Clo=g_pql; scale=QSCALE; }
    else if (which == 1) { Ah=g_kh;  Al=g_kl;  Bhp=g_wh[1]; Blp=g_wl[1]; Chi=g_pkh; Clo=g_pkl; }
    else if (which == 2) { Ah=g_vh;  Al=g_vl;  Bhp=g_wh[2]; Blp=g_wl[2]; Chi=g_pvh; Clo=g_pvl; }
    else                 { Ah=g_poh; Al=g_pol; Bhp=g_wh[3]; Blp=g_wl[3]; }

    const uint32_t sb = smem_u32(smem);
    const int tid = threadIdx.x, wid = tid >> 5, lane = tid & 31;
    const int wm = wid & 3, wn = wid >> 2;
    const int m0 = blockIdx.y * 128, n0 = blockIdx.x * 128;

    float acc[2][8][4];
#pragma unroll
    for (int i = 0; i < 2; i++)
#pragma unroll
        for (int j = 0; j < 8; j++)
#pragma unroll
            for (int q = 0; q < 4; q++) acc[i][j][q] = 0.f;

    const int r0 = tid >> 2, ch0 = tid & 3;
    const int r1 = (tid + 256) >> 2, ch1 = tid & 3;

    auto load_stage = [&](int it, int s) {
        const int kk = it << 5;
        const uint32_t st = sb + s * STG_B;
        const size_t ga0 = (size_t)(m0 + r0) * 1024 + kk + ch0 * 8;
        const size_t ga1 = (size_t)(m0 + r1) * 1024 + kk + ch1 * 8;
        const size_t gb0 = (size_t)(n0 + r0) * 1024 + kk + ch0 * 8;
        const size_t gb1 = (size_t)(n0 + r1) * 1024 + kk + ch1 * 8;
        const uint32_t so0 = r0 * 80 + ch0 * 16;
        const uint32_t so1 = r1 * 80 + ch1 * 16;
        cpa16(st            + so0, Ah  + ga0);
        cpa16(st            + so1, Ah  + ga1);
        cpa16(st +   TEN_B  + so0, Al  + ga0);
        cpa16(st +   TEN_B  + so1, Al  + ga1);
        cpa16(st + 2*TEN_B  + so0, Bhp + gb0);
        cpa16(st + 2*TEN_B  + so1, Bhp + gb1);
        cpa16(st + 3*TEN_B  + so0, Blp + gb0);
        cpa16(st + 3*TEN_B  + so1, Blp + gb1);
        cpa_commit();
    };

    const uint32_t aoff = (uint32_t)(wm * 32 + (lane & 15)) * 80 + ((lane >> 4) << 3) * 2;
    const uint32_t boff = (uint32_t)(wn * 64 + ((lane >> 4) << 3) + (lane & 7)) * 80
                        + (((lane >> 3) & 1) << 3) * 2;

    load_stage(0, 0);
    const int NIT = 32;
    for (int it = 0; it < NIT; it++) {
        const int s = it & 1;
        if (it + 1 < NIT) {
            load_stage(it + 1, s ^ 1);
            asm volatile("cp.async.wait_group 1;" ::: "memory");
        } else {
            asm volatile("cp.async.wait_group 0;" ::: "memory");
        }
        __syncthreads();

        const uint32_t st = sb + s * STG_B;
#pragma unroll
        for (int k16 = 0; k16 < 2; k16++) {
            const uint32_t kb = (uint32_t)(k16 * 16 * 2);
            uint32_t aH[2][4], aL[2][4];
            ldsm4(aH[0], st            + aoff + kb);
            ldsm4(aH[1], st            + aoff + kb + 16 * 80);
            ldsm4(aL[0], st +   TEN_B  + aoff + kb);
            ldsm4(aL[1], st +   TEN_B  + aoff + kb + 16 * 80);
#pragma unroll
            for (int p = 0; p < 4; p++) {
                uint32_t bh[4], bl[4];
                ldsm4(bh, st + 2*TEN_B + boff + kb + (uint32_t)p * 16 * 80);
                ldsm4(bl, st + 3*TEN_B + boff + kb + (uint32_t)p * 16 * 80);
#pragma unroll
                for (int mi = 0; mi < 2; mi++) {
                    mma16816(acc[mi][2*p],   aH[mi], bh[0], bh[1]);
                    mma16816(acc[mi][2*p],   aH[mi], bl[0], bl[1]);
                    mma16816(acc[mi][2*p],   aL[mi], bh[0], bh[1]);
                    mma16816(acc[mi][2*p+1], aH[mi], bh[2], bh[3]);
                    mma16816(acc[mi][2*p+1], aH[mi], bl[2], bl[3]);
                    mma16816(acc[mi][2*p+1], aL[mi], bh[2], bh[3]);
                }
            }
        }
        __syncthreads();
    }

    // epilogue
#pragma unroll
    for (int mi = 0; mi < 2; mi++)
#pragma unroll
        for (int nj = 0; nj < 8; nj++) {
            const int row = m0 + wm * 32 + mi * 16 + (lane >> 2);
            const int col = n0 + wn * 64 + nj * 8 + (lane & 3) * 2;
            if (which == 3) {
                *(float2*)(Cout + (size_t)row * 1024 + col)
                    = make_float2(acc[mi][nj][0], acc[mi][nj][1]);
                *(float2*)(Cout + (size_t)(row + 8) * 1024 + col)
                    = make_float2(acc[mi][nj][2], acc[mi][nj][3]);
            } else {
                uint32_t hh, ll;
                split2(acc[mi][nj][0]*scale, acc[mi][nj][1]*scale, hh, ll);
                *(uint32_t*)(Chi + (size_t)row * 1024 + col) = hh;
                *(uint32_t*)(Clo + (size_t)row * 1024 + col) = ll;
                split2(acc[mi][nj][2]*scale, acc[mi][nj][3]*scale, hh, ll);
                *(uint32_t*)(Chi + (size_t)(row + 8) * 1024 + col) = hh;
                *(uint32_t*)(Clo + (size_t)(row + 8) * 1024 + col) = ll;
            }
        }
}

// ---------------------------------------------------------------------------
// HMMA causal flash attention. 256 threads (8 warps), q-tile 128, key-tile 64.
// Warp w owns q rows w*16..+15. Scores are pre-scaled by log2(e): use ex2.
// K/V cp.async double-buffered; Q fragments hoisted to registers.
// ---------------------------------------------------------------------------
#define T_BYTES (64*144)                 // 9216 per 64-row tensor tile
#define QT_BYTES (128*144)               // 18432 per 128-row Q tile
#define ST_SZ   (4*T_BYTES)              // Kh,Kl,Vh,Vl
#define ATT_SMEM (2*QT_BYTES + 2*ST_SZ)  // 110592

__global__ __launch_bounds__(256) void attn_mma()
{
    extern __shared__ char sm8[];
    const uint32_t sb = smem_u32(sm8);
    const int tid = threadIdx.x, w = tid >> 5, lane = tid & 31;
    const int bh = blockIdx.y, b = bh >> 4, h = bh & 15;
    const int qt = (int)gridDim.x - 1 - blockIdx.x;     // long tiles first
    const int q0 = qt << 7;                              // 128-row q tile
    const size_t rowbase = (size_t)b * SS * HD + h * 64;
    const uint32_t kvb = sb + 2 * QT_BYTES;

    // ---- load Q tile (hi+lo), group 0: 128 rows x 8 chunks ----
#pragma unroll
    for (int i = 0; i < 4; i++) {
        int op = tid + (i << 8);
        int r = op >> 3, ch = op & 7;
        size_t g = rowbase + (size_t)(q0 + r) * HD + ch * 8;
        uint32_t so = (uint32_t)r * 144 + ch * 16;
        cpa16(sb + so,            g_pqh + g);
        cpa16(sb + QT_BYTES + so, g_pql + g);
    }
    cpa_commit();

    auto load_kv = [&](int t, int s) {
        const int j0 = t << 6;
        const uint32_t st = kvb + s * ST_SZ;
#pragma unroll
        for (int i = 0; i < 2; i++) {
            int op = tid + (i << 8);
            int r = op >> 3, ch = op & 7;
            size_t g = rowbase + (size_t)(j0 + r) * HD + ch * 8;
            uint32_t so = (uint32_t)r * 144 + ch * 16;
            cpa16(st              + so, g_pkh + g);
            cpa16(st +   T_BYTES  + so, g_pkl + g);
            cpa16(st + 2*T_BYTES  + so, g_pvh + g);
            cpa16(st + 3*T_BYTES  + so, g_pvl + g);
        }
        cpa_commit();
    };
    load_kv(0, 0);

    const uint32_t qoff = (uint32_t)(w * 16 + (lane & 15)) * 144 + ((lane >> 4) << 4);
    const uint32_t koff = (uint32_t)(((lane >> 4) << 3) + (lane & 7)) * 144
                        + (((lane >> 3) & 1) << 4);
    const uint32_t voff = (uint32_t)((((lane >> 3) & 1) << 3) + (lane & 7)) * 144
                        + ((lane >> 4) << 4);

    // ---- hoist Q fragments ----
    asm volatile("cp.async.wait_group 1;" ::: "memory");   // Q group complete
    __syncthreads();
    uint32_t qH[4][4], qL[4][4];
#pragma unroll
    for (int kc = 0; kc < 4; kc++) {
        ldsm4(qH[kc], sb            + qoff + kc * 32);
        ldsm4(qL[kc], sb + QT_BYTES + qoff + kc * 32);
    }

    float m[2] = {-1e30f, -1e30f}, l[2] = {0.f, 0.f};
    float acc[8][4];
#pragma unroll
    for (int nj = 0; nj < 8; nj++)
#pragma unroll
        for (int e = 0; e < 4; e++) acc[nj][e] = 0.f;

    const int nt = 2 * qt + 2;                 // key tiles
    for (int t = 0; t < nt; t++) {
        const int s = t & 1;
        if (t + 1 < nt) {
            load_kv(t + 1, s ^ 1);
            asm volatile("cp.async.wait_group 1;" ::: "memory");
        } else {
            asm volatile("cp.async.wait_group 0;" ::: "memory");
        }
        __syncthreads();

        // warps 0-3 fully masked on the final tile: skip compute
        if (t == nt - 1 && w < 4) { __syncthreads(); continue; }

        const uint32_t st = kvb + s * ST_SZ;
        const int j0 = t << 6;

        // ---- QK^T ----
        float sf[8][4];
#pragma unroll
        for (int nj = 0; nj < 8; nj++)
#pragma unroll
            for (int e = 0; e < 4; e++) sf[nj][e] = 0.f;
#pragma unroll
        for (int kc = 0; kc < 4; kc++) {
#pragma unroll
            for (int g = 0; g < 4; g++) {
                uint32_t bh[4], bl[4];
                ldsm4(bh, st           + koff + (uint32_t)g * (16*144) + kc * 32);
                ldsm4(bl, st + T_BYTES + koff + (uint32_t)g * (16*144) + kc * 32);
                mma16816(sf[2*g],   qH[kc], bh[0], bh[1]);
                mma16816(sf[2*g],   qH[kc], bl[0], bl[1]);
                mma16816(sf[2*g],   qL[kc], bh[0], bh[1]);
                mma16816(sf[2*g+1], qH[kc], bh[2], bh[3]);
                mma16816(sf[2*g+1], qH[kc], bl[2], bl[3]);
                mma16816(sf[2*g+1], qL[kc], bh[2], bh[3]);
            }
        }

        // ---- causal mask (last two key tiles; global indices) ----
        if (t >= nt - 2) {
            const int rowg = q0 + w * 16 + (lane >> 2);
#pragma unroll
            for (int nj = 0; nj < 8; nj++) {
                const int kg = j0 + nj * 8 + (lane & 3) * 2;
                if (kg     > rowg)     sf[nj][0] = -1e30f;
                if (kg + 1 > rowg)     sf[nj][1] = -1e30f;
                if (kg     > rowg + 8) sf[nj][2] = -1e30f;
                if (kg + 1 > rowg + 8) sf[nj][3] = -1e30f;
            }
        }

        // ---- online softmax (base-2; scores carry log2e) ----
#pragma unroll
        for (int r = 0; r < 2; r++) {
            float mx = -1e30f;
#pragma unroll
            for (int nj = 0; nj < 8; nj++)
                mx = fmaxf(mx, fmaxf(sf[nj][2*r], sf[nj][2*r+1]));
            mx = fmaxf(mx, __shfl_xor_sync(0xffffffffu, mx, 1));
            mx = fmaxf(mx, __shfl_xor_sync(0xffffffffu, mx, 2));
            const float mn = fmaxf(m[r], mx);
            const float corr = ex2(m[r] - mn);
            m[r] = mn;
            float rs = 0.f;
#pragma unroll
            for (int nj = 0; nj < 8; nj++) {
                sf[nj][2*r]   = ex2(sf[nj][2*r]   - mn);
                sf[nj][2*r+1] = ex2(sf[nj][2*r+1] - mn);
                rs += sf[nj][2*r] + sf[nj][2*r+1];
            }
            rs += __shfl_xor_sync(0xffffffffu, rs, 1);
            rs += __shfl_xor_sync(0xffffffffu, rs, 2);
            l[r] = l[r] * corr + rs;
#pragma unroll
            for (int nj = 0; nj < 8; nj++) {
                acc[nj][2*r]   *= corr;
                acc[nj][2*r+1] *= corr;
            }
        }

        // ---- PV ----
#pragma unroll
        for (int kc = 0; kc < 4; kc++) {
            uint32_t ph[4], pl[4];
#pragma unroll
            for (int e = 0; e < 4; e++) {
                const int jj = 2*kc + (e >> 1);
                split2(sf[jj][(e & 1) * 2], sf[jj][(e & 1) * 2 + 1], ph[e], pl[e]);
            }
#pragma unroll
            for (int ng = 0; ng < 4; ng++) {
                uint32_t vh[4], vl[4];
                const uint32_t va = voff + (uint32_t)kc * (16*144) + (uint32_t)ng * 32;
                ldsm4t(vh, st + 2*T_BYTES + va);
                ldsm4t(vl, st + 3*T_BYTES + va);
                mma16816(acc[2*ng],   ph, vh[0], vh[1]);
                mma16816(acc[2*ng],   ph, vl[0], vl[1]);
                mma16816(acc[2*ng],   pl, vh[0], vh[1]);
                mma16816(acc[2*ng+1], ph, vh[2], vh[3]);
                mma16816(acc[2*ng+1], ph, vl[2], vl[3]);
                mma16816(acc[2*ng+1], pl, vh[2], vh[3]);
            }
        }
        __syncthreads();
    }

    // ---- epilogue ----
    const float inv0 = 1.f / l[0], inv1 = 1.f / l[1];
    const size_t base0 = rowbase + (size_t)(q0 + w * 16 + (lane >> 2)) * HD;
    const size_t base1 = base0 + 8 * HD;
#pragma unroll
    for (int nj = 0; nj < 8; nj++) {
        const int col = nj * 8 + (lane & 3) * 2;
        uint32_t hh, ll;
        split2(acc[nj][0] * inv0, acc[nj][1] * inv0, hh, ll);
        *(uint32_t*)(g_poh + base0 + col) = hh;
        *(uint32_t*)(g_pol + base0 + col) = ll;
        split2(acc[nj][2] * inv1, acc[nj][3] * inv1, hh, ll);
        *(uint32_t*)(g_poh + base1 + col) = hh;
        *(uint32_t*)(g_pol + base1 + col) = ll;
    }
}

// ---------------------------------------------------------------------------
// Inputs: queries, keys, values, mask(ignored), W_Q, W_K, W_V, W_O
// ---------------------------------------------------------------------------
extern "C" void kernel_launch(void* const* d_in, const int* in_sizes, int n_in,
                              void* d_out, int out_size)
{
    (void)in_sizes; (void)n_in; (void)out_size;
    const float* q  = (const float*)d_in[0];
    const float* k  = (const float*)d_in[1];
    const float* v  = (const float*)d_in[2];
    const float* wq = (const float*)d_in[4];
    const float* wk = (const float*)d_in[5];
    const float* wv = (const float*)d_in[6];
    const float* wo = (const float*)d_in[7];
    float* out = (float*)d_out;

    cudaFuncSetAttribute(mmagemm,
                         cudaFuncAttributeMaxDynamicSharedMemorySize, G_SMEM);
    cudaFuncSetAttribute(attn_mma,
                         cudaFuncAttributeMaxDynamicSharedMemorySize, ATT_SMEM);

    const int nCvt = (MM * DD / 4) / 256;     // per-tensor float4 blocks

    cvt_hl<<<dim3(nCvt, 3), 256>>>(q, k, v);
    cvtT<<<dim3(32, 32, 4), 256>>>(wq, wk, wv, wo);

    mmagemm<<<dim3(HD / 128, MM / 128, 3), 256, G_SMEM>>>(nullptr, -1);

    attn_mma<<<dim3(SS / 128, BB * HH), 256, ATT_SMEM>>>();

    mmagemm<<<dim3(HD / 128, MM / 128, 1), 256, G_SMEM>>>(out, 3);
}